// round 1
// baseline (speedup 1.0000x reference)
#include <cuda_runtime.h>
#include <math.h>

#define HQn 16
#define HKn 4
#define Dn 64
#define GATE_CHn 12
#define WINDOWn 1024
#define Bn 2
#define Tn 2048
#define En 1024
#define Fn 1536
#define Mn 4096

// Scratch (allocation-free rule: device globals)
__device__ __align__(256) float g_qkv[(size_t)Mn * Fn];
__device__ __align__(256) float g_att[(size_t)Mn * En];

// ---------------------------------------------------------------------------
// SGEMM: C[M,N] = A[M,K] * B[N,K]^T   (both row-major, K contiguous)
// 128x128 block tile, BK=8, 8x8 per-thread microtile, 256 threads.
// Requires M%128==0, N%128==0, K%8==0 (true for all our shapes).
// ---------------------------------------------------------------------------
__global__ __launch_bounds__(256) void sgemm_abt(
    const float* __restrict__ A, const float* __restrict__ Bm,
    float* __restrict__ C, int M, int N, int K)
{
    __shared__ float As[8][128];
    __shared__ float Bs[8][128];
    const int tid = threadIdx.x;
    const int bm = blockIdx.y * 128;
    const int bn = blockIdx.x * 128;
    const int tx = tid & 15;
    const int ty = tid >> 4;
    const int lr = tid >> 1;          // 0..127
    const int lc = (tid & 1) * 4;     // 0 or 4

    float acc[8][8];
    #pragma unroll
    for (int i = 0; i < 8; i++)
        #pragma unroll
        for (int j = 0; j < 8; j++) acc[i][j] = 0.f;

    const float* Aptr = A + (size_t)(bm + lr) * K + lc;
    const float* Bptr = Bm + (size_t)(bn + lr) * K + lc;

    for (int k0 = 0; k0 < K; k0 += 8) {
        float4 av = *(const float4*)(Aptr + k0);
        float4 bv = *(const float4*)(Bptr + k0);
        As[lc + 0][lr] = av.x; As[lc + 1][lr] = av.y;
        As[lc + 2][lr] = av.z; As[lc + 3][lr] = av.w;
        Bs[lc + 0][lr] = bv.x; Bs[lc + 1][lr] = bv.y;
        Bs[lc + 2][lr] = bv.z; Bs[lc + 3][lr] = bv.w;
        __syncthreads();
        #pragma unroll
        for (int kk = 0; kk < 8; kk++) {
            float a[8], b[8];
            *(float4*)&a[0] = *(const float4*)&As[kk][ty * 8];
            *(float4*)&a[4] = *(const float4*)&As[kk][ty * 8 + 4];
            *(float4*)&b[0] = *(const float4*)&Bs[kk][tx * 8];
            *(float4*)&b[4] = *(const float4*)&Bs[kk][tx * 8 + 4];
            #pragma unroll
            for (int i = 0; i < 8; i++)
                #pragma unroll
                for (int j = 0; j < 8; j++)
                    acc[i][j] += a[i] * b[j];
        }
        __syncthreads();
    }
    #pragma unroll
    for (int i = 0; i < 8; i++) {
        float* cp = C + (size_t)(bm + ty * 8 + i) * N + bn + tx * 8;
        float4 v0 = make_float4(acc[i][0], acc[i][1], acc[i][2], acc[i][3]);
        float4 v1 = make_float4(acc[i][4], acc[i][5], acc[i][6], acc[i][7]);
        *(float4*)cp = v0;
        *(float4*)(cp + 4) = v1;
    }
}

// ---------------------------------------------------------------------------
// Fused gate + value_embeds mix, RoPE + RMSNorm (in place on g_qkv).
// One warp per head per token. 4 warps/block, one token per block.
// ---------------------------------------------------------------------------
__global__ __launch_bounds__(128) void rope_rms_gate(
    float* __restrict__ qkv, const float* __restrict__ x,
    const float* __restrict__ ve, const float* __restrict__ rc,
    const float* __restrict__ rs, const float* __restrict__ wg)
{
    const int row = blockIdx.x;            // 0..4095
    const int t = row & (Tn - 1);
    const int warp = threadIdx.x >> 5;
    const int lane = threadIdx.x & 31;

    for (int head = warp; head < HQn + 2 * HKn; head += 4) {
        float* p = qkv + (size_t)row * Fn + head * Dn;
        if (head < HQn + HKn) {
            // q or k head: RoPE then RMSNorm
            float x1 = p[lane], x2 = p[lane + 32];
            float c = rc[t * (Dn / 2) + lane];
            float s = rs[t * (Dn / 2) + lane];
            float y1 = x1 * c - x2 * s;
            float y2 = x1 * s + x2 * c;
            float ss = y1 * y1 + y2 * y2;
            #pragma unroll
            for (int o = 16; o; o >>= 1) ss += __shfl_xor_sync(0xffffffffu, ss, o);
            float r = rsqrtf(ss * (1.0f / Dn) + 1e-8f);
            p[lane] = y1 * r;
            p[lane + 32] = y2 * r;
        } else {
            // v head: v += 3*sigmoid(x[:12] . wg[hv]) * value_embed
            int hv = head - HQn - HKn;
            float pr = (lane < GATE_CHn)
                         ? x[(size_t)row * En + lane] * wg[hv * GATE_CHn + lane]
                         : 0.f;
            #pragma unroll
            for (int o = 16; o; o >>= 1) pr += __shfl_xor_sync(0xffffffffu, pr, o);
            float gate = 3.0f / (1.0f + __expf(-pr));
            const float* vp = ve + (size_t)row * (HKn * Dn) + hv * Dn;
            p[lane]      += gate * vp[lane];
            p[lane + 32] += gate * vp[lane + 32];
        }
    }
}

// ---------------------------------------------------------------------------
// Flash attention, sliding window (j <= i && j >= i - WINDOW), GQA 4:1.
// Block: (q-tile of 64, head, batch). 256 threads as 16x16, 4x4 microtile.
// Smem: Qt/Kt (d-major), Vs (k-major), Pt (k-major transposed), stats, red.
// ---------------------------------------------------------------------------
#define ATTN_SMEM_FLOATS (4096 * 4 + 64 + 64 + 1024 + 1024)
#define ATTN_SMEM_BYTES (ATTN_SMEM_FLOATS * 4)

__global__ __launch_bounds__(256) void attn_kernel(
    const float* __restrict__ qkv, float* __restrict__ out)
{
    extern __shared__ float smbuf[];
    float (*Qt)[64] = (float (*)[64])(smbuf);
    float (*Kt)[64] = (float (*)[64])(smbuf + 4096);
    float (*Vs)[64] = (float (*)[64])(smbuf + 8192);
    float (*Pt)[64] = (float (*)[64])(smbuf + 12288);
    float* row_m = smbuf + 16384;
    float* row_l = smbuf + 16448;
    float* red1  = smbuf + 16512;
    float* red2  = smbuf + 17536;

    const int tid = threadIdx.x;
    const int tx = tid & 15;
    const int ty = tid >> 4;
    const int q0 = blockIdx.x * 64;
    const int h  = blockIdx.y;
    const int bb = blockIdx.z;
    const int hk = h / (HQn / HKn);
    const int qoff = h * Dn;
    const int koff = (HQn + hk) * Dn;
    const int voff = (HQn + HKn + hk) * Dn;
    const int row0 = bb * Tn + q0;

    // Load Q tile (scaled by 1/sqrt(D)=0.125), d-major transpose
    #pragma unroll
    for (int it = 0; it < 4; it++) {
        int f = tid + 256 * it;
        int r = f >> 4, c = (f & 15) * 4;
        float4 v = *(const float4*)(qkv + (size_t)(row0 + r) * Fn + qoff + c);
        Qt[c + 0][r] = v.x * 0.125f;
        Qt[c + 1][r] = v.y * 0.125f;
        Qt[c + 2][r] = v.z * 0.125f;
        Qt[c + 3][r] = v.w * 0.125f;
    }
    if (tid < 64) { row_m[tid] = -1e30f; row_l[tid] = 0.f; }

    float o[4][4];
    #pragma unroll
    for (int a = 0; a < 4; a++)
        #pragma unroll
        for (int c = 0; c < 4; c++) o[a][c] = 0.f;

    const int kt_lo = (q0 >= WINDOWn) ? (q0 - WINDOWn) / 64 : 0;
    const int kt_hi = q0 / 64;
    __syncthreads();

    for (int kt = kt_lo; kt <= kt_hi; kt++) {
        const int k0 = kt * 64;
        const int krow0 = bb * Tn + k0;
        #pragma unroll
        for (int it = 0; it < 4; it++) {
            int f = tid + 256 * it;
            int r = f >> 4, c = (f & 15) * 4;
            float4 kv = *(const float4*)(qkv + (size_t)(krow0 + r) * Fn + koff + c);
            Kt[c + 0][r] = kv.x; Kt[c + 1][r] = kv.y;
            Kt[c + 2][r] = kv.z; Kt[c + 3][r] = kv.w;
            float4 vv = *(const float4*)(qkv + (size_t)(krow0 + r) * Fn + voff + c);
            *(float4*)&Vs[r][c] = vv;
        }
        __syncthreads();

        // S = Q K^T  (4x4 per thread)
        float s[4][4];
        #pragma unroll
        for (int a = 0; a < 4; a++)
            #pragma unroll
            for (int c = 0; c < 4; c++) s[a][c] = 0.f;
        #pragma unroll 8
        for (int d = 0; d < 64; d++) {
            float qa[4], kb[4];
            *(float4*)qa = *(const float4*)&Qt[d][ty * 4];
            *(float4*)kb = *(const float4*)&Kt[d][tx * 4];
            #pragma unroll
            for (int a = 0; a < 4; a++)
                #pragma unroll
                for (int c = 0; c < 4; c++)
                    s[a][c] += qa[a] * kb[c];
        }

        // Sliding-window causal mask
        #pragma unroll
        for (int a = 0; a < 4; a++) {
            int i = q0 + ty * 4 + a;
            #pragma unroll
            for (int c = 0; c < 4; c++) {
                int j = k0 + tx * 4 + c;
                if (j > i || j + WINDOWn < i) s[a][c] = -1e30f;
            }
        }

        // Per-thread row maxes -> smem reduction
        #pragma unroll
        for (int a = 0; a < 4; a++) {
            float m = fmaxf(fmaxf(s[a][0], s[a][1]), fmaxf(s[a][2], s[a][3]));
            red1[(ty * 4 + a) * 16 + tx] = m;
        }
        __syncthreads();

        float mnew[4], alpha[4];
        #pragma unroll
        for (int a = 0; a < 4; a++) {
            int qr = ty * 4 + a;
            float mold = row_m[qr];
            float mt = -1e30f;
            #pragma unroll
            for (int t = 0; t < 16; t++) mt = fmaxf(mt, red1[qr * 16 + t]);
            float mn = fmaxf(mold, mt);
            mnew[a] = mn;
            alpha[a] = __expf(mold - mn);
            float rsum = 0.f;
            #pragma unroll
            for (int c = 0; c < 4; c++) {
                float p = __expf(s[a][c] - mn);
                rsum += p;
                Pt[tx * 4 + c][qr] = p;
            }
            red2[qr * 16 + tx] = rsum;
            #pragma unroll
            for (int c = 0; c < 4; c++) o[a][c] *= alpha[a];
        }
        __syncthreads();

        if (tx == 0) {
            #pragma unroll
            for (int a = 0; a < 4; a++) {
                int qr = ty * 4 + a;
                float ts = 0.f;
                #pragma unroll
                for (int t = 0; t < 16; t++) ts += red2[qr * 16 + t];
                row_m[qr] = mnew[a];
                row_l[qr] = row_l[qr] * alpha[a] + ts;
            }
        }

        // O += P V
        #pragma unroll 8
        for (int k = 0; k < 64; k++) {
            float pa[4], vb[4];
            *(float4*)pa = *(const float4*)&Pt[k][ty * 4];
            *(float4*)vb = *(const float4*)&Vs[k][tx * 4];
            #pragma unroll
            for (int a = 0; a < 4; a++)
                #pragma unroll
                for (int c = 0; c < 4; c++)
                    o[a][c] += pa[a] * vb[c];
        }
        __syncthreads();
    }

    // Normalize + store
    #pragma unroll
    for (int a = 0; a < 4; a++) {
        int qr = ty * 4 + a;
        float inv = 1.0f / row_l[qr];
        float4 v = make_float4(o[a][0] * inv, o[a][1] * inv,
                               o[a][2] * inv, o[a][3] * inv);
        *(float4*)(out + (size_t)(row0 + qr) * En + qoff + tx * 4) = v;
    }
}

// ---------------------------------------------------------------------------
extern "C" void kernel_launch(void* const* d_in, const int* in_sizes, int n_in,
                              void* d_out, int out_size)
{
    (void)in_sizes; (void)n_in; (void)out_size;
    const float* x    = (const float*)d_in[0];
    const float* ve   = (const float*)d_in[1];
    const float* rc   = (const float*)d_in[2];
    const float* rs   = (const float*)d_in[3];
    const float* wqkv = (const float*)d_in[4];
    const float* wg   = (const float*)d_in[5];
    const float* wo   = (const float*)d_in[6];
    float* out = (float*)d_out;

    float *qkv_p = nullptr, *att_p = nullptr;
    cudaGetSymbolAddress((void**)&qkv_p, g_qkv);
    cudaGetSymbolAddress((void**)&att_p, g_att);

    cudaFuncSetAttribute(attn_kernel,
                         cudaFuncAttributeMaxDynamicSharedMemorySize,
                         ATTN_SMEM_BYTES);

    // 1) qkv = x @ w_qkv^T
    sgemm_abt<<<dim3(Fn / 128, Mn / 128), 256>>>(x, wqkv, qkv_p, Mn, Fn, En);
    // 2) gate/value-embed mix + RoPE + RMSNorm (in place)
    rope_rms_gate<<<Mn, 128>>>(qkv_p, x, ve, rc, rs, wg);
    // 3) sliding-window flash attention
    attn_kernel<<<dim3(Tn / 64, HQn, Bn), 256, ATTN_SMEM_BYTES>>>(qkv_p, att_p);
    // 4) out = att @ w_o^T
    sgemm_abt<<<dim3(En / 128, Mn / 128), 256>>>(att_p, wo, out, Mn, En, En);
}

// round 2
// speedup vs baseline: 1.7351x; 1.7351x over previous
#include <cuda_runtime.h>
#include <math.h>

#define HQn 16
#define HKn 4
#define Dn 64
#define GATE_CHn 12
#define WINDOWn 1024
#define Bn 2
#define Tn 2048
#define En 1024
#define Fn 1536
#define Mn 4096

// Scratch (allocation-free rule: device globals)
__device__ __align__(256) float g_qkv[(size_t)Mn * Fn];
__device__ __align__(256) float g_att[(size_t)Mn * En];

// ---------------------------------------------------------------------------
// SGEMM: C[M,N] = A[M,K] * B[N,K]^T   (both row-major, K contiguous)
// 128x128 block tile, BK=8, 8x8 per-thread microtile, 256 threads.
// ---------------------------------------------------------------------------
__global__ __launch_bounds__(256) void sgemm_abt(
    const float* __restrict__ A, const float* __restrict__ Bm,
    float* __restrict__ C, int M, int N, int K)
{
    __shared__ float As[8][128];
    __shared__ float Bs[8][128];
    const int tid = threadIdx.x;
    const int bm = blockIdx.y * 128;
    const int bn = blockIdx.x * 128;
    const int tx = tid & 15;
    const int ty = tid >> 4;
    const int lr = tid >> 1;          // 0..127
    const int lc = (tid & 1) * 4;     // 0 or 4

    float acc[8][8];
    #pragma unroll
    for (int i = 0; i < 8; i++)
        #pragma unroll
        for (int j = 0; j < 8; j++) acc[i][j] = 0.f;

    const float* Aptr = A + (size_t)(bm + lr) * K + lc;
    const float* Bptr = Bm + (size_t)(bn + lr) * K + lc;

    for (int k0 = 0; k0 < K; k0 += 8) {
        float4 av = *(const float4*)(Aptr + k0);
        float4 bv = *(const float4*)(Bptr + k0);
        As[lc + 0][lr] = av.x; As[lc + 1][lr] = av.y;
        As[lc + 2][lr] = av.z; As[lc + 3][lr] = av.w;
        Bs[lc + 0][lr] = bv.x; Bs[lc + 1][lr] = bv.y;
        Bs[lc + 2][lr] = bv.z; Bs[lc + 3][lr] = bv.w;
        __syncthreads();
        #pragma unroll
        for (int kk = 0; kk < 8; kk++) {
            float a[8], b[8];
            *(float4*)&a[0] = *(const float4*)&As[kk][ty * 8];
            *(float4*)&a[4] = *(const float4*)&As[kk][ty * 8 + 4];
            *(float4*)&b[0] = *(const float4*)&Bs[kk][tx * 8];
            *(float4*)&b[4] = *(const float4*)&Bs[kk][tx * 8 + 4];
            #pragma unroll
            for (int i = 0; i < 8; i++)
                #pragma unroll
                for (int j = 0; j < 8; j++)
                    acc[i][j] += a[i] * b[j];
        }
        __syncthreads();
    }
    #pragma unroll
    for (int i = 0; i < 8; i++) {
        float* cp = C + (size_t)(bm + ty * 8 + i) * N + bn + tx * 8;
        *(float4*)cp = make_float4(acc[i][0], acc[i][1], acc[i][2], acc[i][3]);
        *(float4*)(cp + 4) = make_float4(acc[i][4], acc[i][5], acc[i][6], acc[i][7]);
    }
}

// ---------------------------------------------------------------------------
// Fused gate + value_embeds mix, RoPE + RMSNorm (in place on g_qkv).
// ---------------------------------------------------------------------------
__global__ __launch_bounds__(128) void rope_rms_gate(
    float* __restrict__ qkv, const float* __restrict__ x,
    const float* __restrict__ ve, const float* __restrict__ rc,
    const float* __restrict__ rs, const float* __restrict__ wg)
{
    const int row = blockIdx.x;            // 0..4095
    const int t = row & (Tn - 1);
    const int warp = threadIdx.x >> 5;
    const int lane = threadIdx.x & 31;

    for (int head = warp; head < HQn + 2 * HKn; head += 4) {
        float* p = qkv + (size_t)row * Fn + head * Dn;
        if (head < HQn + HKn) {
            float x1 = p[lane], x2 = p[lane + 32];
            float c = rc[t * (Dn / 2) + lane];
            float s = rs[t * (Dn / 2) + lane];
            float y1 = x1 * c - x2 * s;
            float y2 = x1 * s + x2 * c;
            float ss = y1 * y1 + y2 * y2;
            #pragma unroll
            for (int o = 16; o; o >>= 1) ss += __shfl_xor_sync(0xffffffffu, ss, o);
            float r = rsqrtf(ss * (1.0f / Dn) + 1e-8f);
            p[lane] = y1 * r;
            p[lane + 32] = y2 * r;
        } else {
            int hv = head - HQn - HKn;
            float pr = (lane < GATE_CHn)
                         ? x[(size_t)row * En + lane] * wg[hv * GATE_CHn + lane]
                         : 0.f;
            #pragma unroll
            for (int o = 16; o; o >>= 1) pr += __shfl_xor_sync(0xffffffffu, pr, o);
            float gate = 3.0f / (1.0f + __expf(-pr));
            const float* vp = ve + (size_t)row * (HKn * Dn) + hv * Dn;
            p[lane]      += gate * vp[lane];
            p[lane + 32] += gate * vp[lane + 32];
        }
    }
}

// ---------------------------------------------------------------------------
// Flash attention v2: 128-query x 64-key tiles, 8x4 microtile, register
// softmax with shfl row reductions, padded smem to kill transpose-store
// bank conflicts, P stored q-major (conflict-free both directions).
// ---------------------------------------------------------------------------
#define QTILE 128
#define KTILE 64
#define KT_PAD 68      // row length for d-major K (floats)
#define QT_PAD 132     // row length for d-major Q (floats)
#define VS_PAD 68

#define SM_QT   0
#define SM_KT   (SM_QT + 64 * QT_PAD)
#define SM_VS   (SM_KT + 64 * KT_PAD)
#define SM_PS   (SM_VS + 64 * VS_PAD)
#define ATTN_SMEM_FLOATS (SM_PS + QTILE * KTILE)
#define ATTN_SMEM_BYTES (ATTN_SMEM_FLOATS * 4)

__global__ __launch_bounds__(256, 2) void attn_kernel(
    const float* __restrict__ qkv, float* __restrict__ out)
{
    extern __shared__ float smbuf[];
    float (*Qt)[QT_PAD] = (float (*)[QT_PAD])(smbuf + SM_QT);   // [d][q]
    float (*Kt)[KT_PAD] = (float (*)[KT_PAD])(smbuf + SM_KT);   // [d][k]
    float (*Vs)[VS_PAD] = (float (*)[VS_PAD])(smbuf + SM_VS);   // [k][d]
    float (*Ps)[KTILE]  = (float (*)[KTILE])(smbuf + SM_PS);    // [q][k]

    const int tid = threadIdx.x;
    const int tx = tid & 15;           // key / d-col group
    const int ty = tid >> 4;           // query group (8 rows each)
    const int q0 = blockIdx.x * QTILE;
    const int h  = blockIdx.y;
    const int bb = blockIdx.z;
    const int hk = h >> 2;             // HQ/HK = 4
    const int qoff = h * Dn;
    const int koff = (HQn + hk) * Dn;
    const int voff = (HQn + HKn + hk) * Dn;
    const int row0 = bb * Tn + q0;

    // Load Q tile (scaled), transpose to d-major
    #pragma unroll
    for (int it = 0; it < 8; it++) {
        int f = tid + 256 * it;
        int r = f >> 4, c = (f & 15) * 4;
        float4 v = *(const float4*)(qkv + (size_t)(row0 + r) * Fn + qoff + c);
        Qt[c + 0][r] = v.x * 0.125f;
        Qt[c + 1][r] = v.y * 0.125f;
        Qt[c + 2][r] = v.z * 0.125f;
        Qt[c + 3][r] = v.w * 0.125f;
    }

    float m_s[8], l_s[8], o[8][4];
    #pragma unroll
    for (int a = 0; a < 8; a++) {
        m_s[a] = -1e30f; l_s[a] = 0.f;
        #pragma unroll
        for (int c = 0; c < 4; c++) o[a][c] = 0.f;
    }

    const int kt_lo = (q0 > WINDOWn) ? ((q0 - WINDOWn) >> 6) : 0;
    const int kt_hi = (q0 + QTILE - 1) >> 6;

    for (int kt = kt_lo; kt <= kt_hi; kt++) {
        const int k0 = kt * 64;
        const int krow0 = bb * Tn + k0;
        // Load K (transpose to d-major) and V (k-major)
        #pragma unroll
        for (int it = 0; it < 4; it++) {
            int f = tid + 256 * it;
            int r = f >> 4, c = (f & 15) * 4;
            float4 kv = *(const float4*)(qkv + (size_t)(krow0 + r) * Fn + koff + c);
            Kt[c + 0][r] = kv.x; Kt[c + 1][r] = kv.y;
            Kt[c + 2][r] = kv.z; Kt[c + 3][r] = kv.w;
            float4 vv = *(const float4*)(qkv + (size_t)(krow0 + r) * Fn + voff + c);
            *(float4*)&Vs[r][c] = vv;
        }
        __syncthreads();

        // S = Q K^T : 8x4 per thread
        float s[8][4];
        #pragma unroll
        for (int a = 0; a < 8; a++)
            #pragma unroll
            for (int c = 0; c < 4; c++) s[a][c] = 0.f;
        #pragma unroll 8
        for (int d = 0; d < 64; d++) {
            float qa[8], kb[4];
            *(float4*)&qa[0] = *(const float4*)&Qt[d][ty * 8];
            *(float4*)&qa[4] = *(const float4*)&Qt[d][ty * 8 + 4];
            *(float4*)&kb[0] = *(const float4*)&Kt[d][tx * 4];
            #pragma unroll
            for (int a = 0; a < 8; a++)
                #pragma unroll
                for (int c = 0; c < 4; c++)
                    s[a][c] += qa[a] * kb[c];
        }

        // Mask + online softmax (register state, shfl reductions in 16-lane row group)
        #pragma unroll
        for (int a = 0; a < 8; a++) {
            const int i = q0 + ty * 8 + a;
            #pragma unroll
            for (int c = 0; c < 4; c++) {
                int j = k0 + tx * 4 + c;
                if (j > i || j + WINDOWn < i) s[a][c] = -1e30f;
            }
            float m = fmaxf(fmaxf(s[a][0], s[a][1]), fmaxf(s[a][2], s[a][3]));
            #pragma unroll
            for (int off = 8; off; off >>= 1)
                m = fmaxf(m, __shfl_xor_sync(0xffffffffu, m, off));
            float mn = fmaxf(m_s[a], m);
            float alpha = __expf(m_s[a] - mn);
            m_s[a] = mn;
            const bool live = mn > -1e29f;
            float p[4], rsum = 0.f;
            #pragma unroll
            for (int c = 0; c < 4; c++) {
                p[c] = live ? __expf(s[a][c] - mn) : 0.f;
                rsum += p[c];
            }
            *(float4*)&Ps[ty * 8 + a][tx * 4] = make_float4(p[0], p[1], p[2], p[3]);
            #pragma unroll
            for (int off = 8; off; off >>= 1)
                rsum += __shfl_xor_sync(0xffffffffu, rsum, off);
            l_s[a] = l_s[a] * alpha + rsum;
            #pragma unroll
            for (int c = 0; c < 4; c++) o[a][c] *= alpha;
        }
        __syncthreads();

        // O += P V : iterate k in chunks of 4, P broadcast reads (float4)
        #pragma unroll 4
        for (int k4 = 0; k4 < 64; k4 += 4) {
            float pa[8][4], vb[4][4];
            #pragma unroll
            for (int a = 0; a < 8; a++)
                *(float4*)&pa[a][0] = *(const float4*)&Ps[ty * 8 + a][k4];
            #pragma unroll
            for (int kk = 0; kk < 4; kk++)
                *(float4*)&vb[kk][0] = *(const float4*)&Vs[k4 + kk][tx * 4];
            #pragma unroll
            for (int a = 0; a < 8; a++)
                #pragma unroll
                for (int kk = 0; kk < 4; kk++)
                    #pragma unroll
                    for (int c = 0; c < 4; c++)
                        o[a][c] += pa[a][kk] * vb[kk][c];
        }
        __syncthreads();
    }

    // Normalize + store
    #pragma unroll
    for (int a = 0; a < 8; a++) {
        float inv = 1.0f / l_s[a];
        float4 v = make_float4(o[a][0] * inv, o[a][1] * inv,
                               o[a][2] * inv, o[a][3] * inv);
        *(float4*)(out + (size_t)(row0 + ty * 8 + a) * En + qoff + tx * 4) = v;
    }
}

// ---------------------------------------------------------------------------
extern "C" void kernel_launch(void* const* d_in, const int* in_sizes, int n_in,
                              void* d_out, int out_size)
{
    (void)in_sizes; (void)n_in; (void)out_size;
    const float* x    = (const float*)d_in[0];
    const float* ve   = (const float*)d_in[1];
    const float* rc   = (const float*)d_in[2];
    const float* rs   = (const float*)d_in[3];
    const float* wqkv = (const float*)d_in[4];
    const float* wg   = (const float*)d_in[5];
    const float* wo   = (const float*)d_in[6];
    float* out = (float*)d_out;

    float *qkv_p = nullptr, *att_p = nullptr;
    cudaGetSymbolAddress((void**)&qkv_p, g_qkv);
    cudaGetSymbolAddress((void**)&att_p, g_att);

    cudaFuncSetAttribute(attn_kernel,
                         cudaFuncAttributeMaxDynamicSharedMemorySize,
                         ATTN_SMEM_BYTES);

    sgemm_abt<<<dim3(Fn / 128, Mn / 128), 256>>>(x, wqkv, qkv_p, Mn, Fn, En);
    rope_rms_gate<<<Mn, 128>>>(qkv_p, x, ve, rc, rs, wg);
    attn_kernel<<<dim3(Tn / QTILE, HQn, Bn), 256, ATTN_SMEM_BYTES>>>(qkv_p, att_p);
    sgemm_abt<<<dim3(En / 128, Mn / 128), 256>>>(att_p, wo, out, Mn, En, En);
}

// round 3
// speedup vs baseline: 2.4407x; 1.4067x over previous
#include <cuda_runtime.h>
#include <math.h>
#include <stdint.h>

#define HQn 16
#define HKn 4
#define Dn 64
#define GATE_CHn 12
#define WINDOWn 1024
#define Bn 2
#define Tn 2048
#define En 1024
#define Fn 1536
#define Mn 4096

// Scratch (allocation-free rule: device globals)
__device__ __align__(256) float g_qkv[(size_t)Mn * Fn];
__device__ __align__(256) float g_att[(size_t)Mn * En];

// ---------------------------------------------------------------------------
// TF32 helpers
// ---------------------------------------------------------------------------
__device__ __forceinline__ uint32_t f2tf32(float x) {
    uint32_t r;
    asm("cvt.rna.tf32.f32 %0, %1;" : "=r"(r) : "f"(x));
    return r;
}

__device__ __forceinline__ void mma_tf32(float* d, const uint32_t* a,
                                         const uint32_t* b) {
    asm volatile(
        "mma.sync.aligned.m16n8k8.row.col.f32.tf32.tf32.f32 "
        "{%0,%1,%2,%3}, {%4,%5,%6,%7}, {%8,%9}, {%0,%1,%2,%3};\n"
        : "+f"(d[0]), "+f"(d[1]), "+f"(d[2]), "+f"(d[3])
        : "r"(a[0]), "r"(a[1]), "r"(a[2]), "r"(a[3]), "r"(b[0]), "r"(b[1]));
}

// ---------------------------------------------------------------------------
// TF32 tensor-core GEMM: C[M,N] = A[M,K] * B[N,K]^T (both K contiguous)
// 128x128 tile, BK=32, 8 warps: warp tile 32(M) x 64(N) = 2x8 m16n8k8.
// Smem k-major with row stride 136 words -> conflict-free frag reads/writes.
// ---------------------------------------------------------------------------
#define BKg 32
__global__ __launch_bounds__(256) void gemm_tf32(
    const float* __restrict__ A, const float* __restrict__ Bm,
    float* __restrict__ C, int M, int N, int K)
{
    __shared__ uint32_t As[BKg][136];
    __shared__ uint32_t Bs[BKg][136];

    const int tid = threadIdx.x;
    const int lane = tid & 31;
    const int warp = tid >> 5;
    const int wm = (warp & 3) * 32;
    const int wn = (warp >> 2) * 64;
    const int bm = blockIdx.y * 128;
    const int bn = blockIdx.x * 128;

    const int lm = tid & 127;        // row loaded by this thread
    const int lk = (tid >> 7) * 4;   // k sub-offset: 0 or 4

    float acc[2][8][4];
    #pragma unroll
    for (int mt = 0; mt < 2; mt++)
        #pragma unroll
        for (int nt = 0; nt < 8; nt++)
            #pragma unroll
            for (int i = 0; i < 4; i++) acc[mt][nt][i] = 0.f;

    const float* Ap = A + (size_t)(bm + lm) * K + lk;
    const float* Bp = Bm + (size_t)(bn + lm) * K + lk;

    for (int k0 = 0; k0 < K; k0 += BKg) {
        #pragma unroll
        for (int kk = 0; kk < BKg; kk += 8) {
            float4 av = *(const float4*)(Ap + k0 + kk);
            float4 bv = *(const float4*)(Bp + k0 + kk);
            int kr = kk + lk;
            As[kr + 0][lm] = f2tf32(av.x);
            As[kr + 1][lm] = f2tf32(av.y);
            As[kr + 2][lm] = f2tf32(av.z);
            As[kr + 3][lm] = f2tf32(av.w);
            Bs[kr + 0][lm] = f2tf32(bv.x);
            Bs[kr + 1][lm] = f2tf32(bv.y);
            Bs[kr + 2][lm] = f2tf32(bv.z);
            Bs[kr + 3][lm] = f2tf32(bv.w);
        }
        __syncthreads();

        #pragma unroll
        for (int ks = 0; ks < BKg; ks += 8) {
            uint32_t afr[2][4], bfr[8][2];
            const int kk = ks + (lane & 3);
            #pragma unroll
            for (int mt = 0; mt < 2; mt++) {
                int m = wm + mt * 16 + (lane >> 2);
                afr[mt][0] = As[kk][m];
                afr[mt][1] = As[kk][m + 8];
                afr[mt][2] = As[kk + 4][m];
                afr[mt][3] = As[kk + 4][m + 8];
            }
            #pragma unroll
            for (int nt = 0; nt < 8; nt++) {
                int n = wn + nt * 8 + (lane >> 2);
                bfr[nt][0] = Bs[kk][n];
                bfr[nt][1] = Bs[kk + 4][n];
            }
            #pragma unroll
            for (int mt = 0; mt < 2; mt++)
                #pragma unroll
                for (int nt = 0; nt < 8; nt++)
                    mma_tf32(acc[mt][nt], afr[mt], bfr[nt]);
        }
        __syncthreads();
    }

    // Epilogue
    #pragma unroll
    for (int mt = 0; mt < 2; mt++) {
        const int r0 = bm + wm + mt * 16 + (lane >> 2);
        #pragma unroll
        for (int nt = 0; nt < 8; nt++) {
            const int c0 = bn + wn + nt * 8 + 2 * (lane & 3);
            *(float2*)(C + (size_t)r0 * N + c0) =
                make_float2(acc[mt][nt][0], acc[mt][nt][1]);
            *(float2*)(C + (size_t)(r0 + 8) * N + c0) =
                make_float2(acc[mt][nt][2], acc[mt][nt][3]);
        }
    }
}

// ---------------------------------------------------------------------------
// Fused gate + value_embeds mix, RoPE + RMSNorm (in place on g_qkv).
// ---------------------------------------------------------------------------
__global__ __launch_bounds__(128) void rope_rms_gate(
    float* __restrict__ qkv, const float* __restrict__ x,
    const float* __restrict__ ve, const float* __restrict__ rc,
    const float* __restrict__ rs, const float* __restrict__ wg)
{
    const int row = blockIdx.x;
    const int t = row & (Tn - 1);
    const int warp = threadIdx.x >> 5;
    const int lane = threadIdx.x & 31;

    for (int head = warp; head < HQn + 2 * HKn; head += 4) {
        float* p = qkv + (size_t)row * Fn + head * Dn;
        if (head < HQn + HKn) {
            float x1 = p[lane], x2 = p[lane + 32];
            float c = rc[t * (Dn / 2) + lane];
            float s = rs[t * (Dn / 2) + lane];
            float y1 = x1 * c - x2 * s;
            float y2 = x1 * s + x2 * c;
            float ss = y1 * y1 + y2 * y2;
            #pragma unroll
            for (int o = 16; o; o >>= 1) ss += __shfl_xor_sync(0xffffffffu, ss, o);
            float r = rsqrtf(ss * (1.0f / Dn) + 1e-8f);
            p[lane] = y1 * r;
            p[lane + 32] = y2 * r;
        } else {
            int hv = head - HQn - HKn;
            float pr = (lane < GATE_CHn)
                         ? x[(size_t)row * En + lane] * wg[hv * GATE_CHn + lane]
                         : 0.f;
            #pragma unroll
            for (int o = 16; o; o >>= 1) pr += __shfl_xor_sync(0xffffffffu, pr, o);
            float gate = 3.0f / (1.0f + __expf(-pr));
            const float* vp = ve + (size_t)row * (HKn * Dn) + hv * Dn;
            p[lane]      += gate * vp[lane];
            p[lane + 32] += gate * vp[lane + 32];
        }
    }
}

// ---------------------------------------------------------------------------
// Flash attention: 128-query x 64-key tiles, 8x4 microtile, register softmax.
// ---------------------------------------------------------------------------
#define QTILE 128
#define KTILE 64
#define KT_PAD 68
#define QT_PAD 132
#define VS_PAD 68

#define SM_QT   0
#define SM_KT   (SM_QT + 64 * QT_PAD)
#define SM_VS   (SM_KT + 64 * KT_PAD)
#define SM_PS   (SM_VS + 64 * VS_PAD)
#define ATTN_SMEM_FLOATS (SM_PS + QTILE * KTILE)
#define ATTN_SMEM_BYTES (ATTN_SMEM_FLOATS * 4)

__global__ __launch_bounds__(256, 2) void attn_kernel(
    const float* __restrict__ qkv, float* __restrict__ out)
{
    extern __shared__ float smbuf[];
    float (*Qt)[QT_PAD] = (float (*)[QT_PAD])(smbuf + SM_QT);
    float (*Kt)[KT_PAD] = (float (*)[KT_PAD])(smbuf + SM_KT);
    float (*Vs)[VS_PAD] = (float (*)[VS_PAD])(smbuf + SM_VS);
    float (*Ps)[KTILE]  = (float (*)[KTILE])(smbuf + SM_PS);

    const int tid = threadIdx.x;
    const int tx = tid & 15;
    const int ty = tid >> 4;
    const int q0 = blockIdx.x * QTILE;
    const int h  = blockIdx.y;
    const int bb = blockIdx.z;
    const int hk = h >> 2;
    const int qoff = h * Dn;
    const int koff = (HQn + hk) * Dn;
    const int voff = (HQn + HKn + hk) * Dn;
    const int row0 = bb * Tn + q0;

    #pragma unroll
    for (int it = 0; it < 8; it++) {
        int f = tid + 256 * it;
        int r = f >> 4, c = (f & 15) * 4;
        float4 v = *(const float4*)(qkv + (size_t)(row0 + r) * Fn + qoff + c);
        Qt[c + 0][r] = v.x * 0.125f;
        Qt[c + 1][r] = v.y * 0.125f;
        Qt[c + 2][r] = v.z * 0.125f;
        Qt[c + 3][r] = v.w * 0.125f;
    }

    float m_s[8], l_s[8], o[8][4];
    #pragma unroll
    for (int a = 0; a < 8; a++) {
        m_s[a] = -1e30f; l_s[a] = 0.f;
        #pragma unroll
        for (int c = 0; c < 4; c++) o[a][c] = 0.f;
    }

    const int kt_lo = (q0 > WINDOWn) ? ((q0 - WINDOWn) >> 6) : 0;
    const int kt_hi = (q0 + QTILE - 1) >> 6;

    for (int kt = kt_lo; kt <= kt_hi; kt++) {
        const int k0 = kt * 64;
        const int krow0 = bb * Tn + k0;
        #pragma unroll
        for (int it = 0; it < 4; it++) {
            int f = tid + 256 * it;
            int r = f >> 4, c = (f & 15) * 4;
            float4 kv = *(const float4*)(qkv + (size_t)(krow0 + r) * Fn + koff + c);
            Kt[c + 0][r] = kv.x; Kt[c + 1][r] = kv.y;
            Kt[c + 2][r] = kv.z; Kt[c + 3][r] = kv.w;
            float4 vv = *(const float4*)(qkv + (size_t)(krow0 + r) * Fn + voff + c);
            *(float4*)&Vs[r][c] = vv;
        }
        __syncthreads();

        float s[8][4];
        #pragma unroll
        for (int a = 0; a < 8; a++)
            #pragma unroll
            for (int c = 0; c < 4; c++) s[a][c] = 0.f;
        #pragma unroll 8
        for (int d = 0; d < 64; d++) {
            float qa[8], kb[4];
            *(float4*)&qa[0] = *(const float4*)&Qt[d][ty * 8];
            *(float4*)&qa[4] = *(const float4*)&Qt[d][ty * 8 + 4];
            *(float4*)&kb[0] = *(const float4*)&Kt[d][tx * 4];
            #pragma unroll
            for (int a = 0; a < 8; a++)
                #pragma unroll
                for (int c = 0; c < 4; c++)
                    s[a][c] += qa[a] * kb[c];
        }

        #pragma unroll
        for (int a = 0; a < 8; a++) {
            const int i = q0 + ty * 8 + a;
            #pragma unroll
            for (int c = 0; c < 4; c++) {
                int j = k0 + tx * 4 + c;
                if (j > i || j + WINDOWn < i) s[a][c] = -1e30f;
            }
            float m = fmaxf(fmaxf(s[a][0], s[a][1]), fmaxf(s[a][2], s[a][3]));
            #pragma unroll
            for (int off = 8; off; off >>= 1)
                m = fmaxf(m, __shfl_xor_sync(0xffffffffu, m, off));
            float mn = fmaxf(m_s[a], m);
            float alpha = __expf(m_s[a] - mn);
            m_s[a] = mn;
            const bool live = mn > -1e29f;
            float p[4], rsum = 0.f;
            #pragma unroll
            for (int c = 0; c < 4; c++) {
                p[c] = live ? __expf(s[a][c] - mn) : 0.f;
                rsum += p[c];
            }
            *(float4*)&Ps[ty * 8 + a][tx * 4] = make_float4(p[0], p[1], p[2], p[3]);
            #pragma unroll
            for (int off = 8; off; off >>= 1)
                rsum += __shfl_xor_sync(0xffffffffu, rsum, off);
            l_s[a] = l_s[a] * alpha + rsum;
            #pragma unroll
            for (int c = 0; c < 4; c++) o[a][c] *= alpha;
        }
        __syncthreads();

        #pragma unroll 4
        for (int k4 = 0; k4 < 64; k4 += 4) {
            float pa[8][4], vb[4][4];
            #pragma unroll
            for (int a = 0; a < 8; a++)
                *(float4*)&pa[a][0] = *(const float4*)&Ps[ty * 8 + a][k4];
            #pragma unroll
            for (int kk = 0; kk < 4; kk++)
                *(float4*)&vb[kk][0] = *(const float4*)&Vs[k4 + kk][tx * 4];
            #pragma unroll
            for (int a = 0; a < 8; a++)
                #pragma unroll
                for (int kk = 0; kk < 4; kk++)
                    #pragma unroll
                    for (int c = 0; c < 4; c++)
                        o[a][c] += pa[a][kk] * vb[kk][c];
        }
        __syncthreads();
    }

    #pragma unroll
    for (int a = 0; a < 8; a++) {
        float inv = 1.0f / l_s[a];
        float4 v = make_float4(o[a][0] * inv, o[a][1] * inv,
                               o[a][2] * inv, o[a][3] * inv);
        *(float4*)(out + (size_t)(row0 + ty * 8 + a) * En + qoff + tx * 4) = v;
    }
}

// ---------------------------------------------------------------------------
extern "C" void kernel_launch(void* const* d_in, const int* in_sizes, int n_in,
                              void* d_out, int out_size)
{
    (void)in_sizes; (void)n_in; (void)out_size;
    const float* x    = (const float*)d_in[0];
    const float* ve   = (const float*)d_in[1];
    const float* rc   = (const float*)d_in[2];
    const float* rs   = (const float*)d_in[3];
    const float* wqkv = (const float*)d_in[4];
    const float* wg   = (const float*)d_in[5];
    const float* wo   = (const float*)d_in[6];
    float* out = (float*)d_out;

    float *qkv_p = nullptr, *att_p = nullptr;
    cudaGetSymbolAddress((void**)&qkv_p, g_qkv);
    cudaGetSymbolAddress((void**)&att_p, g_att);

    cudaFuncSetAttribute(attn_kernel,
                         cudaFuncAttributeMaxDynamicSharedMemorySize,
                         ATTN_SMEM_BYTES);

    gemm_tf32<<<dim3(Fn / 128, Mn / 128), 256>>>(x, wqkv, qkv_p, Mn, Fn, En);
    rope_rms_gate<<<Mn, 128>>>(qkv_p, x, ve, rc, rs, wg);
    attn_kernel<<<dim3(Tn / QTILE, HQn, Bn), 256, ATTN_SMEM_BYTES>>>(qkv_p, att_p);
    gemm_tf32<<<dim3(En / 128, Mn / 128), 256>>>(att_p, wo, out, Mn, En, En);
}